// round 1
// baseline (speedup 1.0000x reference)
#include <cuda_runtime.h>
#include <cuda_bf16.h>

#define Bc 8
#define Nmax 34000
#define Mc 64
#define EPSL 1e-7f

// Scratch (no allocation allowed): decoded boxes, per-anchor atan, scatter target, partials.
__device__ float4       g_pb[Bc * Nmax];
__device__ float        g_at1[Bc * Nmax];
__device__ unsigned int g_it[Bc * Nmax];
__device__ float        g_part[Bc * 4];

// ---------------------------------------------------------------------------
// Kernel 1: DFL decode -> pb (xyxy), anchor atan, and zero the scatter buffer.
// boxes: [B, 64, N]  (channel stride N, coalesced across n)
// ---------------------------------------------------------------------------
__global__ void k_decode(const float* __restrict__ boxes, int N) {
    int idx = blockIdx.x * blockDim.x + threadIdx.x;
    if (idx >= Bc * N) return;
    int b = idx / N;
    int n = idx - b * N;
    const float* base = boxes + (size_t)b * 64 * N + n;

    float pb[4];
#pragma unroll
    for (int k = 0; k < 4; k++) {
        float x[16];
#pragma unroll
        for (int r = 0; r < 16; r++) x[r] = base[(size_t)(k * 16 + r) * N];
        float mx = x[0];
#pragma unroll
        for (int r = 1; r < 16; r++) mx = fmaxf(mx, x[r]);
        float s = 0.f, e = 0.f;
#pragma unroll
        for (int r = 0; r < 16; r++) {
            float t = expf(x[r] - mx);
            s += t;
            e += t * (float)r;
        }
        pb[k] = e / s;
    }
    float w1 = pb[2] - pb[0];
    float h1 = pb[3] - pb[1];
    g_pb[idx]  = make_float4(pb[0], pb[1], pb[2], pb[3]);
    g_at1[idx] = atanf(w1 / (h1 + EPSL));
    g_it[idx]  = 0u;   // zero scatter target every replay (graph-safe)
}

// ---------------------------------------------------------------------------
// Kernel 2: one block per (m, b). Compute ciou vs all N anchors, keep exact
// top-10 (tie-break: lower anchor index, matching lax.top_k), scatter
// positive values via atomicMax on float bits.
// ---------------------------------------------------------------------------
__global__ __launch_bounds__(256) void k_topk(const float* __restrict__ targets, int N) {
    const int m = blockIdx.x;
    const int b = blockIdx.y;
    const int tid = threadIdx.x;

    const float* t = targets + ((size_t)b * Mc + m) * 4;
    const float x21 = t[0], y21 = t[1], x22 = t[2], y22 = t[3];
    const float w2 = x22 - x21, h2 = y22 - y21;
    const float area2 = w2 * h2;
    const float at2 = atanf(w2 / (h2 + EPSL));
    const float sx = x21 + x22, sy = y21 + y22;
    const float VP = 4.0f / (float)(M_PI * M_PI);

    unsigned long long top[10];
#pragma unroll
    for (int j = 0; j < 10; j++) top[j] = 0ull;

    const float4* __restrict__ pb = g_pb + (size_t)b * N;
    const float*  __restrict__ a1 = g_at1 + (size_t)b * N;

    for (int n = tid; n < N; n += 256) {
        float4 p = pb[n];
        float at1 = a1[n];
        float w1 = p.z - p.x, h1 = p.w - p.y;

        float iw = fminf(p.z, x22) - fmaxf(p.x, x21); iw = fmaxf(iw, 0.f);
        float ih = fminf(p.w, y22) - fmaxf(p.y, y21); ih = fmaxf(ih, 0.f);
        float inter = iw * ih;
        float uni = w1 * h1 + area2 - inter + EPSL;
        float iou = inter / uni;

        float cw = fmaxf(p.z, x22) - fminf(p.x, x21);
        float ch = fmaxf(p.w, y22) - fminf(p.y, y21);
        float c2 = cw * cw + ch * ch + EPSL;

        float dx = sx - p.x - p.z;
        float dy = sy - p.y - p.w;
        float rho2 = (dx * dx + dy * dy) * 0.25f;

        float d = at2 - at1;
        float v = VP * d * d;
        float alpha = v / (v - iou + 1.0f + EPSL);
        float ciou = iou - rho2 / c2 - alpha * v;

        // order-preserving key: larger key <=> larger float; ~idx => lower idx wins ties
        unsigned u = __float_as_uint(ciou);
        unsigned key = (u & 0x80000000u) ? ~u : (u | 0x80000000u);
        unsigned long long pk =
            ((unsigned long long)key << 32) | (unsigned long long)(0xFFFFFFFFu - (unsigned)n);

        if (pk > top[9]) {
#pragma unroll
            for (int j = 0; j < 10; j++) {
                if (pk > top[j]) { unsigned long long tmp = top[j]; top[j] = pk; pk = tmp; }
            }
        }
    }

    __shared__ unsigned long long cand[2560];
    __shared__ unsigned long long red[256];
#pragma unroll
    for (int j = 0; j < 10; j++) cand[tid * 10 + j] = top[j];
    __syncthreads();

    for (int round = 0; round < 10; ++round) {
        unsigned long long mx = 0ull;
        for (int j = tid; j < 2560; j += 256) {
            unsigned long long c = cand[j];
            if (c > mx) mx = c;
        }
        red[tid] = mx;
        __syncthreads();
        for (int s = 128; s > 0; s >>= 1) {
            if (tid < s && red[tid + s] > red[tid]) red[tid] = red[tid + s];
            __syncthreads();
        }
        unsigned long long best = red[0];
        __syncthreads();

        unsigned key = (unsigned)(best >> 32);
        if (key <= 0x80000000u) break;  // value <= 0: nothing left to scatter

        if (tid == 0) {
            unsigned n = 0xFFFFFFFFu - (unsigned)(best & 0xFFFFFFFFull);
            // key ^ 0x80000000 == original positive-float bits
            atomicMax(&g_it[(size_t)b * N + n], key ^ 0x80000000u);
        }
        for (int j = tid; j < 2560; j += 256)
            if (cand[j] == best) cand[j] = 0ull;
        __syncthreads();
    }
}

// ---------------------------------------------------------------------------
// Kernel 3: per-batch reductions (npos, box-sum, bce-sum). Deterministic
// fixed-order tree reduce.
// ---------------------------------------------------------------------------
__global__ __launch_bounds__(256) void k_reduce(const float* __restrict__ scores, int N) {
    const int b = blockIdx.x;
    const int tid = threadIdx.x;
    float np = 0.f, bs = 0.f, bc = 0.f;
    const unsigned int* __restrict__ it = g_it + (size_t)b * N;
    const float* __restrict__ sc = scores + (size_t)b * N;
    for (int n = tid; n < N; n += 256) {
        float iv = __uint_as_float(it[n]);
        float s = sc[n];
        if (iv > 0.f) { np += 1.f; bs += 1.f - iv; }
        bc += fmaxf(s, 0.f) - s * iv + log1pf(expf(-fabsf(s)));
    }
    __shared__ float r0[256], r1[256], r2[256];
    r0[tid] = np; r1[tid] = bs; r2[tid] = bc;
    __syncthreads();
    for (int s = 128; s > 0; s >>= 1) {
        if (tid < s) { r0[tid] += r0[tid + s]; r1[tid] += r1[tid + s]; r2[tid] += r2[tid + s]; }
        __syncthreads();
    }
    if (tid == 0) {
        g_part[b * 4 + 0] = r0[0];
        g_part[b * 4 + 1] = r1[0];
        g_part[b * 4 + 2] = r2[0];
    }
}

// ---------------------------------------------------------------------------
// Kernel 4: finalize -> (total, box_loss, obj_loss)
// ---------------------------------------------------------------------------
__global__ void k_final(float* out, int out_size, int N) {
    if (threadIdx.x == 0 && blockIdx.x == 0) {
        float box = 0.f, obj = 0.f;
        for (int b = 0; b < Bc; b++) {
            float np = g_part[b * 4 + 0];
            float bs = g_part[b * 4 + 1];
            float bcs = g_part[b * 4 + 2];
            box += (np > 0.f) ? bs / fmaxf(np, 1.f) : 0.f;
            obj += bcs / (float)N;
        }
        float total = (7.5f * box + 1.0f * obj) / (float)Bc;
        out[0] = total;
        if (out_size > 1) out[1] = box;
        if (out_size > 2) out[2] = obj;
    }
}

extern "C" void kernel_launch(void* const* d_in, const int* in_sizes, int n_in,
                              void* d_out, int out_size) {
    const float* boxes   = (const float*)d_in[0];   // [8, 64, N]
    const float* scores  = (const float*)d_in[1];   // [8, N]
    const float* targets = (const float*)d_in[2];   // [8, 64, 4]
    int N = in_sizes[1] / Bc;
    if (N > Nmax) N = Nmax;

    int tot = Bc * N;
    k_decode<<<(tot + 255) / 256, 256>>>(boxes, N);
    dim3 g2(Mc, Bc);
    k_topk<<<g2, 256>>>(targets, N);
    k_reduce<<<Bc, 256>>>(scores, N);
    k_final<<<1, 32>>>((float*)d_out, out_size, N);
}

// round 2
// speedup vs baseline: 1.1099x; 1.1099x over previous
#include <cuda_runtime.h>
#include <cuda_bf16.h>

#define Bc 8
#define Nmax 34000
#define Mc 64
#define EPSL 1e-7f

// Scratch (no allocation allowed)
__device__ float4       g_pb[Bc * Nmax];
__device__ float        g_at1[Bc * Nmax];
__device__ unsigned int g_it[Bc * Nmax];
__device__ float        g_part[Bc * 4];
__device__ unsigned int g_cnt;

// ---------------------------------------------------------------------------
// Kernel 1: DFL decode -> pb (xyxy), anchor atan, zero scatter buffer+counter.
// boxes: [B, 64, N]  (channel stride N, coalesced across n)
// ---------------------------------------------------------------------------
__global__ __launch_bounds__(256) void k_decode(const float* __restrict__ boxes, int N) {
    int idx = blockIdx.x * blockDim.x + threadIdx.x;
    if (idx == 0) g_cnt = 0u;
    if (idx >= Bc * N) return;
    int b = idx / N;
    int n = idx - b * N;
    const float* base = boxes + (size_t)b * 64 * N + n;

    float pb[4];
#pragma unroll
    for (int k = 0; k < 4; k++) {
        float s = 0.f, e = 0.f;
#pragma unroll
        for (int r = 0; r < 16; r++) {
            float t = __expf(base[(size_t)(k * 16 + r) * N]);
            s += t;
            e += t * (float)r;
        }
        pb[k] = __fdividef(e, s);
    }
    float w1 = pb[2] - pb[0];
    float h1 = pb[3] - pb[1];
    g_pb[idx]  = make_float4(pb[0], pb[1], pb[2], pb[3]);
    g_at1[idx] = atanf(__fdividef(w1, h1 + EPSL));
    g_it[idx]  = 0u;   // zero scatter target every replay (graph-safe)
}

// ---------------------------------------------------------------------------
// Kernel 2: one block per (m, b). ciou vs all N anchors, exact top-10
// (tie-break: lower anchor index, matching lax.top_k), scatter positive
// values via atomicMax on float bits (order-preserving for non-neg floats).
// ---------------------------------------------------------------------------
__global__ __launch_bounds__(256) void k_topk(const float* __restrict__ targets, int N) {
    const int m = blockIdx.x;
    const int b = blockIdx.y;
    const int tid  = threadIdx.x;
    const int lane = tid & 31;
    const int wid  = tid >> 5;

    const float* t = targets + ((size_t)b * Mc + m) * 4;
    const float x21 = t[0], y21 = t[1], x22 = t[2], y22 = t[3];
    const float w2 = x22 - x21, h2 = y22 - y21;
    const float area2 = w2 * h2;
    const float at2 = atanf(__fdividef(w2, h2 + EPSL));
    const float sx = x21 + x22, sy = y21 + y22;
    const float VP = 4.0f / (float)(M_PI * M_PI);

    unsigned long long top[10];
#pragma unroll
    for (int j = 0; j < 10; j++) top[j] = 0ull;

    const float4* __restrict__ pb = g_pb + (size_t)b * N;
    const float*  __restrict__ a1 = g_at1 + (size_t)b * N;

    for (int n = tid; n < N; n += 256) {
        float4 p = pb[n];
        float at1 = a1[n];
        float w1 = p.z - p.x, h1 = p.w - p.y;

        float iw = fminf(p.z, x22) - fmaxf(p.x, x21); iw = fmaxf(iw, 0.f);
        float ih = fminf(p.w, y22) - fmaxf(p.y, y21); ih = fmaxf(ih, 0.f);
        float inter = iw * ih;
        float uni = w1 * h1 + area2 - inter + EPSL;
        float iou = __fdividef(inter, uni);

        float cw = fmaxf(p.z, x22) - fminf(p.x, x21);
        float ch = fmaxf(p.w, y22) - fminf(p.y, y21);
        float c2 = cw * cw + ch * ch + EPSL;

        float dx = sx - p.x - p.z;
        float dy = sy - p.y - p.w;
        float rho2 = (dx * dx + dy * dy) * 0.25f;

        float d = at2 - at1;
        float v = VP * d * d;
        float av = __fdividef(v * v, v - iou + 1.0f + EPSL);   // alpha*v
        float ciou = iou - __fdividef(rho2, c2) - av;

        // order-preserving key: larger key <=> larger float; ~idx => lower idx wins ties
        unsigned u = __float_as_uint(ciou);
        unsigned key = (u & 0x80000000u) ? ~u : (u | 0x80000000u);
        unsigned long long pk =
            ((unsigned long long)key << 32) | (unsigned long long)(0xFFFFFFFFu - (unsigned)n);

        if (pk > top[9]) {
#pragma unroll
            for (int j = 0; j < 10; j++) {
                if (pk > top[j]) { unsigned long long tmp = top[j]; top[j] = pk; pk = tmp; }
            }
        }
    }

    __shared__ unsigned long long cand[2560];
    __shared__ unsigned long long wval[8];
    __shared__ int                wpos[8];
    __shared__ unsigned long long s_best;
    __shared__ int                s_bpos;

#pragma unroll
    for (int j = 0; j < 10; j++) cand[tid * 10 + j] = top[j];
    __syncthreads();

    for (int round = 0; round < 10; ++round) {
        // local argmax over this thread's 10 slots
        unsigned long long mx = 0ull; int mp = tid * 10;
#pragma unroll
        for (int j = 0; j < 10; j++) {
            unsigned long long c = cand[tid * 10 + j];
            if (c > mx) { mx = c; mp = tid * 10 + j; }
        }
        // warp argmax
#pragma unroll
        for (int off = 16; off > 0; off >>= 1) {
            unsigned long long ov = __shfl_down_sync(0xFFFFFFFFu, mx, off);
            int op = __shfl_down_sync(0xFFFFFFFFu, mp, off);
            if (ov > mx) { mx = ov; mp = op; }
        }
        if (lane == 0) { wval[wid] = mx; wpos[wid] = mp; }
        __syncthreads();
        if (wid == 0) {
            unsigned long long v2 = (lane < 8) ? wval[lane] : 0ull;
            int p2 = (lane < 8) ? wpos[lane] : 0;
#pragma unroll
            for (int off = 4; off > 0; off >>= 1) {
                unsigned long long ov = __shfl_down_sync(0xFFFFFFFFu, v2, off);
                int op = __shfl_down_sync(0xFFFFFFFFu, p2, off);
                if (ov > v2) { v2 = ov; p2 = op; }
            }
            if (lane == 0) { s_best = v2; s_bpos = p2; }
        }
        __syncthreads();
        unsigned long long best = s_best;
        int bp = s_bpos;
        unsigned key = (unsigned)(best >> 32);
        if (key <= 0x80000000u) break;  // value <= 0: nothing left to scatter

        if (tid == 0) {
            unsigned n = 0xFFFFFFFFu - (unsigned)(best & 0xFFFFFFFFull);
            // key ^ 0x80000000 == original positive-float bits
            atomicMax(&g_it[(size_t)b * N + n], key ^ 0x80000000u);
        }
        if (tid == bp / 10) cand[bp] = 0ull;  // clear only the winning slot
        __syncthreads();
    }
}

// ---------------------------------------------------------------------------
// Kernel 3: per-batch reductions + fused finalize (last block pattern).
// ---------------------------------------------------------------------------
__global__ __launch_bounds__(256) void k_reduce(const float* __restrict__ scores, int N,
                                                float* out, int out_size) {
    const int b = blockIdx.x;
    const int tid = threadIdx.x;
    float np = 0.f, bs = 0.f, bc = 0.f;
    const unsigned int* __restrict__ it = g_it + (size_t)b * N;
    const float* __restrict__ sc = scores + (size_t)b * N;
    for (int n = tid; n < N; n += 256) {
        float iv = __uint_as_float(it[n]);
        float s = sc[n];
        if (iv > 0.f) { np += 1.f; bs += 1.f - iv; }
        bc += fmaxf(s, 0.f) - s * iv + log1pf(__expf(-fabsf(s)));
    }
    __shared__ float r0[256], r1[256], r2[256];
    __shared__ int s_last;
    r0[tid] = np; r1[tid] = bs; r2[tid] = bc;
    __syncthreads();
    for (int s = 128; s > 0; s >>= 1) {
        if (tid < s) { r0[tid] += r0[tid + s]; r1[tid] += r1[tid + s]; r2[tid] += r2[tid + s]; }
        __syncthreads();
    }
    if (tid == 0) {
        g_part[b * 4 + 0] = r0[0];
        g_part[b * 4 + 1] = r1[0];
        g_part[b * 4 + 2] = r2[0];
        __threadfence();
        unsigned int done = atomicAdd(&g_cnt, 1u);
        s_last = (done == Bc - 1) ? 1 : 0;
    }
    __syncthreads();
    if (s_last && tid == 0) {
        float box = 0.f, obj = 0.f;
        for (int bb = 0; bb < Bc; bb++) {
            float nps = g_part[bb * 4 + 0];
            float bss = g_part[bb * 4 + 1];
            float bcs = g_part[bb * 4 + 2];
            box += (nps > 0.f) ? __fdividef(bss, fmaxf(nps, 1.f)) : 0.f;
            obj += bcs / (float)N;
        }
        float total = (7.5f * box + 1.0f * obj) / (float)Bc;
        out[0] = total;
        if (out_size > 1) out[1] = box;
        if (out_size > 2) out[2] = obj;
    }
}

extern "C" void kernel_launch(void* const* d_in, const int* in_sizes, int n_in,
                              void* d_out, int out_size) {
    const float* boxes   = (const float*)d_in[0];   // [8, 64, N]
    const float* scores  = (const float*)d_in[1];   // [8, N]
    const float* targets = (const float*)d_in[2];   // [8, 64, 4]
    int N = in_sizes[1] / Bc;
    if (N > Nmax) N = Nmax;

    int tot = Bc * N;
    k_decode<<<(tot + 255) / 256, 256>>>(boxes, N);
    dim3 g2(Mc, Bc);
    k_topk<<<g2, 256>>>(targets, N);
    k_reduce<<<Bc, 256>>>(scores, N, (float*)d_out, out_size);
}

// round 3
// speedup vs baseline: 1.5272x; 1.3759x over previous
#include <cuda_runtime.h>
#include <cuda_bf16.h>

#define Bc 8
#define Nmax 34000
#define Mc 64
#define EPSL 1e-7f
#define FULLM 0xFFFFFFFFu
#define CHUNK 2048

// Scratch (static device globals; no allocation allowed)
__device__ float4       g_pb[Bc * Nmax];
__device__ float        g_at1[Bc * Nmax];
__device__ unsigned int g_it[Bc * Nmax];
__device__ float        g_part[Bc * 4];
__device__ unsigned int g_cnt;
__device__ unsigned int g_cnt_m[Bc * Mc];                 // survivor count per (b,m)
__device__ unsigned int g_list[(size_t)Bc * Mc * Nmax];   // survivor anchor indices

// ---------------------------------------------------------------------------
// Kernel 1 (vectorized): DFL decode 4 anchors/thread -> pb, atan, zero buffers.
// boxes: [B, 64, N], n fastest. Requires N % 4 == 0.
// ---------------------------------------------------------------------------
__global__ __launch_bounds__(256) void k_decode4(const float* __restrict__ boxes, int N) {
    int idx = blockIdx.x * blockDim.x + threadIdx.x;
    if (idx < Bc * Mc) g_cnt_m[idx] = 0u;
    if (idx == Bc * Mc) g_cnt = 0u;
    int nq = N >> 2;
    if (idx >= Bc * nq) return;
    int b = idx / nq;
    int n = (idx - b * nq) << 2;
    const float* base = boxes + (size_t)b * 64 * N + n;

    float out[4][4];   // [k][j] j = anchor within quad
#pragma unroll
    for (int k = 0; k < 4; k++) {
        float s0=0.f,s1=0.f,s2=0.f,s3=0.f, e0=0.f,e1=0.f,e2=0.f,e3=0.f;
#pragma unroll
        for (int r = 0; r < 16; r++) {
            float4 x = *(const float4*)(base + (size_t)(k * 16 + r) * N);
            float fr = (float)r;
            float t0 = __expf(x.x), t1 = __expf(x.y), t2 = __expf(x.z), t3 = __expf(x.w);
            s0 += t0; s1 += t1; s2 += t2; s3 += t3;
            e0 += t0 * fr; e1 += t1 * fr; e2 += t2 * fr; e3 += t3 * fr;
        }
        out[k][0] = __fdividef(e0, s0);
        out[k][1] = __fdividef(e1, s1);
        out[k][2] = __fdividef(e2, s2);
        out[k][3] = __fdividef(e3, s3);
    }
    size_t o = (size_t)b * N + n;
#pragma unroll
    for (int j = 0; j < 4; j++) {
        float4 p = make_float4(out[0][j], out[1][j], out[2][j], out[3][j]);
        g_pb[o + j]  = p;
        g_at1[o + j] = atanf(__fdividef(p.z - p.x, p.w - p.y + EPSL));
    }
    *(uint4*)&g_it[o] = make_uint4(0u, 0u, 0u, 0u);
}

// Scalar fallback (N % 4 != 0)
__global__ __launch_bounds__(256) void k_decode1(const float* __restrict__ boxes, int N) {
    int idx = blockIdx.x * blockDim.x + threadIdx.x;
    if (idx < Bc * Mc) g_cnt_m[idx] = 0u;
    if (idx == Bc * Mc) g_cnt = 0u;
    if (idx >= Bc * N) return;
    int b = idx / N;
    int n = idx - b * N;
    const float* base = boxes + (size_t)b * 64 * N + n;
    float pb[4];
#pragma unroll
    for (int k = 0; k < 4; k++) {
        float s = 0.f, e = 0.f;
#pragma unroll
        for (int r = 0; r < 16; r++) {
            float t = __expf(base[(size_t)(k * 16 + r) * N]);
            s += t; e += t * (float)r;
        }
        pb[k] = __fdividef(e, s);
    }
    g_pb[idx]  = make_float4(pb[0], pb[1], pb[2], pb[3]);
    g_at1[idx] = atanf(__fdividef(pb[2] - pb[0], pb[3] - pb[1] + EPSL));
    g_it[idx]  = 0u;
}

// ---------------------------------------------------------------------------
// Kernel 2: filter. Grid (ceil(N/CHUNK), B). Phase 1 compacts non-degenerate
// predicted boxes of this N-chunk into smem; phase 2 tests each vs all 64
// targets and appends overlapping (inter>0) pairs to per-(b,m) lists.
// Only pairs with inter>0 can have ciou>0 and thus affect the loss.
// ---------------------------------------------------------------------------
__global__ __launch_bounds__(256) void k_filter(const float* __restrict__ targets, int N) {
    const int b   = blockIdx.y;
    const int c0  = blockIdx.x * CHUNK;
    const int tid = threadIdx.x;
    const int lane = tid & 31;

    __shared__ float  s_x1[Mc], s_y1[Mc], s_x2[Mc], s_y2[Mc];
    __shared__ float4 s_p[CHUNK];
    __shared__ int    s_n[CHUNK];
    __shared__ int    s_cnt;

    if (tid < Mc) {
        const float* t = targets + ((size_t)b * Mc + tid) * 4;
        s_x1[tid] = t[0]; s_y1[tid] = t[1]; s_x2[tid] = t[2]; s_y2[tid] = t[3];
    }
    if (tid == 0) s_cnt = 0;
    __syncthreads();

    const float4* __restrict__ pb = g_pb + (size_t)b * N;
    int cend = min(c0 + CHUNK, N);
    for (int n = c0 + tid; n < cend; n += 256) {
        float4 p = pb[n];
        if (p.z > p.x && p.w > p.y) {
            int k = atomicAdd(&s_cnt, 1);
            s_p[k] = p; s_n[k] = n;
        }
    }
    __syncthreads();
    const int cnt = s_cnt;
    const unsigned lmask = (1u << lane) - 1u;

    for (int i0 = 0; i0 < cnt; i0 += 256) {
        int i = i0 + tid;
        bool have = i < cnt;
        float4 p = have ? s_p[i] : make_float4(0.f, 0.f, 0.f, 0.f);
        unsigned n = have ? (unsigned)s_n[i] : 0u;
#pragma unroll 4
        for (int m = 0; m < Mc; m++) {
            float iw = fminf(p.z, s_x2[m]) - fmaxf(p.x, s_x1[m]);
            float ih = fminf(p.w, s_y2[m]) - fmaxf(p.y, s_y1[m]);
            bool hit = have && (iw > 0.f) && (ih > 0.f);
            unsigned msk = __ballot_sync(FULLM, hit);
            if (msk) {
                int leader = __ffs(msk) - 1;
                unsigned base = 0;
                if (lane == leader)
                    base = atomicAdd(&g_cnt_m[b * Mc + m], (unsigned)__popc(msk));
                base = __shfl_sync(FULLM, base, leader);
                if (hit)
                    g_list[(size_t)(b * Mc + m) * Nmax + base + __popc(msk & lmask)] = n;
            }
        }
    }
}

// ---------------------------------------------------------------------------
// Kernel 3: per-(b,m) exact top-10 ciou over the survivor list, scatter
// positive values via atomicMax on float bits.
// ---------------------------------------------------------------------------
__global__ __launch_bounds__(256) void k_ciou(const float* __restrict__ targets, int N) {
    const int m = blockIdx.x;
    const int b = blockIdx.y;
    const int bm = b * Mc + m;
    const int tid  = threadIdx.x;
    const int lane = tid & 31;
    const int wid  = tid >> 5;

    const float* t = targets + (size_t)bm * 4;
    const float x21 = t[0], y21 = t[1], x22 = t[2], y22 = t[3];
    const float w2 = x22 - x21, h2 = y22 - y21;
    const float area2 = w2 * h2;
    const float at2 = atanf(__fdividef(w2, h2 + EPSL));
    const float sx = x21 + x22, sy = y21 + y22;
    const float VP = 4.0f / (float)(M_PI * M_PI);

    unsigned cnt = g_cnt_m[bm];
    if (cnt > (unsigned)N) cnt = (unsigned)N;

    unsigned long long top[10];
#pragma unroll
    for (int j = 0; j < 10; j++) top[j] = 0ull;

    const float4* __restrict__ pb = g_pb + (size_t)b * N;
    const float*  __restrict__ a1 = g_at1 + (size_t)b * N;
    const unsigned* __restrict__ lst = g_list + (size_t)bm * Nmax;

    for (unsigned i = tid; i < cnt; i += 256) {
        unsigned n = lst[i];
        float4 p = pb[n];
        float at1 = a1[n];
        float w1 = p.z - p.x, h1 = p.w - p.y;

        float iw = fminf(p.z, x22) - fmaxf(p.x, x21); iw = fmaxf(iw, 0.f);
        float ih = fminf(p.w, y22) - fmaxf(p.y, y21); ih = fmaxf(ih, 0.f);
        float inter = iw * ih;
        float uni = w1 * h1 + area2 - inter + EPSL;
        float iou = __fdividef(inter, uni);

        float cw = fmaxf(p.z, x22) - fminf(p.x, x21);
        float ch = fmaxf(p.w, y22) - fminf(p.y, y21);
        float c2 = cw * cw + ch * ch + EPSL;

        float dx = sx - p.x - p.z;
        float dy = sy - p.y - p.w;
        float rho2 = (dx * dx + dy * dy) * 0.25f;

        float d = at2 - at1;
        float v = VP * d * d;
        float av = __fdividef(v * v, v - iou + 1.0f + EPSL);
        float ciou = iou - __fdividef(rho2, c2) - av;

        unsigned u = __float_as_uint(ciou);
        unsigned key = (u & 0x80000000u) ? ~u : (u | 0x80000000u);
        unsigned long long pk =
            ((unsigned long long)key << 32) | (unsigned long long)(0xFFFFFFFFu - n);

        if (pk > top[9]) {
#pragma unroll
            for (int j = 0; j < 10; j++) {
                if (pk > top[j]) { unsigned long long tmp = top[j]; top[j] = pk; pk = tmp; }
            }
        }
    }

    __shared__ unsigned long long cand[2560];
    __shared__ unsigned long long wval[8];
    __shared__ int                wpos[8];
    __shared__ unsigned long long s_best;
    __shared__ int                s_bpos;

#pragma unroll
    for (int j = 0; j < 10; j++) cand[tid * 10 + j] = top[j];
    __syncthreads();

    for (int round = 0; round < 10; ++round) {
        unsigned long long mx = 0ull; int mp = tid * 10;
#pragma unroll
        for (int j = 0; j < 10; j++) {
            unsigned long long c = cand[tid * 10 + j];
            if (c > mx) { mx = c; mp = tid * 10 + j; }
        }
#pragma unroll
        for (int off = 16; off > 0; off >>= 1) {
            unsigned long long ov = __shfl_down_sync(FULLM, mx, off);
            int op = __shfl_down_sync(FULLM, mp, off);
            if (ov > mx) { mx = ov; mp = op; }
        }
        if (lane == 0) { wval[wid] = mx; wpos[wid] = mp; }
        __syncthreads();
        if (wid == 0) {
            unsigned long long v2 = (lane < 8) ? wval[lane] : 0ull;
            int p2 = (lane < 8) ? wpos[lane] : 0;
#pragma unroll
            for (int off = 4; off > 0; off >>= 1) {
                unsigned long long ov = __shfl_down_sync(FULLM, v2, off);
                int op = __shfl_down_sync(FULLM, p2, off);
                if (ov > v2) { v2 = ov; p2 = op; }
            }
            if (lane == 0) { s_best = v2; s_bpos = p2; }
        }
        __syncthreads();
        unsigned long long best = s_best;
        int bp = s_bpos;
        unsigned key = (unsigned)(best >> 32);
        if (key <= 0x80000000u) break;   // value <= 0: nothing left to scatter

        if (tid == 0) {
            unsigned n = 0xFFFFFFFFu - (unsigned)(best & 0xFFFFFFFFull);
            atomicMax(&g_it[(size_t)b * N + n], key ^ 0x80000000u);
        }
        if (tid == bp / 10) cand[bp] = 0ull;
        __syncthreads();
    }
}

// ---------------------------------------------------------------------------
// Kernel 4: per-batch reductions + fused finalize (last-block pattern).
// ---------------------------------------------------------------------------
__global__ __launch_bounds__(256) void k_reduce(const float* __restrict__ scores, int N,
                                                float* out, int out_size) {
    const int b = blockIdx.x;
    const int tid = threadIdx.x;
    float np = 0.f, bs = 0.f, bc = 0.f;
    const unsigned int* __restrict__ it = g_it + (size_t)b * N;
    const float* __restrict__ sc = scores + (size_t)b * N;
    for (int n = tid; n < N; n += 256) {
        float iv = __uint_as_float(it[n]);
        float s = sc[n];
        if (iv > 0.f) { np += 1.f; bs += 1.f - iv; }
        bc += fmaxf(s, 0.f) - s * iv + log1pf(__expf(-fabsf(s)));
    }
    __shared__ float r0[256], r1[256], r2[256];
    __shared__ int s_last;
    r0[tid] = np; r1[tid] = bs; r2[tid] = bc;
    __syncthreads();
    for (int s = 128; s > 0; s >>= 1) {
        if (tid < s) { r0[tid] += r0[tid + s]; r1[tid] += r1[tid + s]; r2[tid] += r2[tid + s]; }
        __syncthreads();
    }
    if (tid == 0) {
        g_part[b * 4 + 0] = r0[0];
        g_part[b * 4 + 1] = r1[0];
        g_part[b * 4 + 2] = r2[0];
        __threadfence();
        unsigned int done = atomicAdd(&g_cnt, 1u);
        s_last = (done == Bc - 1) ? 1 : 0;
    }
    __syncthreads();
    if (s_last && tid == 0) {
        float box = 0.f, obj = 0.f;
        for (int bb = 0; bb < Bc; bb++) {
            float nps = g_part[bb * 4 + 0];
            float bss = g_part[bb * 4 + 1];
            float bcs = g_part[bb * 4 + 2];
            box += (nps > 0.f) ? __fdividef(bss, fmaxf(nps, 1.f)) : 0.f;
            obj += bcs / (float)N;
        }
        float total = (7.5f * box + 1.0f * obj) / (float)Bc;
        out[0] = total;
        if (out_size > 1) out[1] = box;
        if (out_size > 2) out[2] = obj;
    }
}

extern "C" void kernel_launch(void* const* d_in, const int* in_sizes, int n_in,
                              void* d_out, int out_size) {
    const float* boxes   = (const float*)d_in[0];   // [8, 64, N]
    const float* scores  = (const float*)d_in[1];   // [8, N]
    const float* targets = (const float*)d_in[2];   // [8, 64, 4]
    int N = in_sizes[1] / Bc;
    if (N > Nmax) N = Nmax;

    if ((N & 3) == 0) {
        int tot = Bc * (N >> 2);
        k_decode4<<<(tot + 255) / 256, 256>>>(boxes, N);
    } else {
        int tot = Bc * N;
        k_decode1<<<(tot + 255) / 256, 256>>>(boxes, N);
    }
    dim3 gf((N + CHUNK - 1) / CHUNK, Bc);
    k_filter<<<gf, 256>>>(targets, N);
    dim3 gc(Mc, Bc);
    k_ciou<<<gc, 256>>>(targets, N);
    k_reduce<<<Bc, 256>>>(scores, N, (float*)d_out, out_size);
}

// round 7
// speedup vs baseline: 1.8094x; 1.1848x over previous
#include <cuda_runtime.h>
#include <cuda_bf16.h>

#define Bc 8
#define Nmax 34000
#define Mc 64
#define EPSL 1e-7f
#define FULLM 0xFFFFFFFFu
#define CHUNK 2048
#define NCH 48          // reduce chunks per batch

// Scratch (static device globals; no allocation allowed)
__device__ float4       g_pb[Bc * Nmax];
__device__ float        g_at1[Bc * Nmax];
__device__ unsigned int g_it[Bc * Nmax];
__device__ float        g_part2[Bc * NCH * 3];
__device__ unsigned int g_cnt;
__device__ unsigned int g_cnt_m[Bc * Mc];                 // survivor count per (b,m)
__device__ unsigned int g_list[(size_t)Bc * Mc * Nmax];   // survivor anchor indices

// ---------------------------------------------------------------------------
// Kernel 1 (vectorized): DFL decode 4 anchors/thread -> pb, atan, zero buffers.
// boxes: [B, 64, N], n fastest. Requires N % 4 == 0.
// ---------------------------------------------------------------------------
__global__ __launch_bounds__(256) void k_decode4(const float* __restrict__ boxes, int N) {
    int idx = blockIdx.x * blockDim.x + threadIdx.x;
    if (idx < Bc * Mc) g_cnt_m[idx] = 0u;
    if (idx == Bc * Mc) g_cnt = 0u;
    int nq = N >> 2;
    if (idx >= Bc * nq) return;
    int b = idx / nq;
    int n = (idx - b * nq) << 2;
    const float* base = boxes + (size_t)b * 64 * N + n;

    float out[4][4];   // [k][j] j = anchor within quad
#pragma unroll
    for (int k = 0; k < 4; k++) {
        float s0=0.f,s1=0.f,s2=0.f,s3=0.f, e0=0.f,e1=0.f,e2=0.f,e3=0.f;
#pragma unroll
        for (int r = 0; r < 16; r++) {
            float4 x = *(const float4*)(base + (size_t)(k * 16 + r) * N);
            float fr = (float)r;
            float t0 = __expf(x.x), t1 = __expf(x.y), t2 = __expf(x.z), t3 = __expf(x.w);
            s0 += t0; s1 += t1; s2 += t2; s3 += t3;
            e0 += t0 * fr; e1 += t1 * fr; e2 += t2 * fr; e3 += t3 * fr;
        }
        out[k][0] = __fdividef(e0, s0);
        out[k][1] = __fdividef(e1, s1);
        out[k][2] = __fdividef(e2, s2);
        out[k][3] = __fdividef(e3, s3);
    }
    size_t o = (size_t)b * N + n;
#pragma unroll
    for (int j = 0; j < 4; j++) {
        float4 p = make_float4(out[0][j], out[1][j], out[2][j], out[3][j]);
        g_pb[o + j]  = p;
        g_at1[o + j] = atanf(__fdividef(p.z - p.x, p.w - p.y + EPSL));
    }
    *(uint4*)&g_it[o] = make_uint4(0u, 0u, 0u, 0u);
}

// Scalar fallback (N % 4 != 0)
__global__ __launch_bounds__(256) void k_decode1(const float* __restrict__ boxes, int N) {
    int idx = blockIdx.x * blockDim.x + threadIdx.x;
    if (idx < Bc * Mc) g_cnt_m[idx] = 0u;
    if (idx == Bc * Mc) g_cnt = 0u;
    if (idx >= Bc * N) return;
    int b = idx / N;
    int n = idx - b * N;
    const float* base = boxes + (size_t)b * 64 * N + n;
    float pb[4];
#pragma unroll
    for (int k = 0; k < 4; k++) {
        float s = 0.f, e = 0.f;
#pragma unroll
        for (int r = 0; r < 16; r++) {
            float t = __expf(base[(size_t)(k * 16 + r) * N]);
            s += t; e += t * (float)r;
        }
        pb[k] = __fdividef(e, s);
    }
    g_pb[idx]  = make_float4(pb[0], pb[1], pb[2], pb[3]);
    g_at1[idx] = atanf(__fdividef(pb[2] - pb[0], pb[3] - pb[1] + EPSL));
    g_it[idx]  = 0u;
}

// ---------------------------------------------------------------------------
// Kernel 2: filter. Grid (ceil(N/CHUNK), B). Phase 1 compacts non-degenerate
// predicted boxes into smem (warp-aggregated, WARP-UNIFORM loop); phase 2
// tests vs all 64 targets, appends overlapping (inter>0) pairs to per-(b,m)
// lists. Only pairs with inter>0 can have ciou>0 and thus affect the loss.
// ---------------------------------------------------------------------------
__global__ __launch_bounds__(256) void k_filter(const float* __restrict__ targets, int N) {
    const int b   = blockIdx.y;
    const int c0  = blockIdx.x * CHUNK;
    const int tid = threadIdx.x;
    const int lane = tid & 31;
    const unsigned lmask = (1u << lane) - 1u;

    __shared__ float  s_x1[Mc], s_y1[Mc], s_x2[Mc], s_y2[Mc];
    __shared__ float4 s_p[CHUNK];
    __shared__ int    s_n[CHUNK];
    __shared__ int    s_cnt;

    if (tid < Mc) {
        const float* t = targets + ((size_t)b * Mc + tid) * 4;
        s_x1[tid] = t[0]; s_y1[tid] = t[1]; s_x2[tid] = t[2]; s_y2[tid] = t[3];
    }
    if (tid == 0) s_cnt = 0;
    __syncthreads();

    const float4* __restrict__ pb = g_pb + (size_t)b * N;
    const int cend = min(c0 + CHUNK, N);
    const int len  = cend - c0;
    const int iters = (len + 255) / 256;         // uniform across the block
    for (int it = 0; it < iters; it++) {
        int n = c0 + it * 256 + tid;
        bool in = n < cend;
        float4 p = in ? pb[n] : make_float4(0.f, 0.f, 0.f, 0.f);
        bool v = in && (p.z > p.x) && (p.w > p.y);
        unsigned msk = __ballot_sync(FULLM, v);   // full warp always present
        if (msk) {
            int leader = __ffs(msk) - 1;
            int base = 0;
            if (lane == leader) base = atomicAdd(&s_cnt, __popc(msk));
            base = __shfl_sync(FULLM, base, leader);
            if (v) {
                int k = base + __popc(msk & lmask);
                s_p[k] = p; s_n[k] = n;
            }
        }
    }
    __syncthreads();
    const int cnt = s_cnt;

    for (int i0 = 0; i0 < cnt; i0 += 256) {
        int i = i0 + tid;
        bool have = i < cnt;
        float4 p = have ? s_p[i] : make_float4(0.f, 0.f, 0.f, 0.f);
        unsigned n = have ? (unsigned)s_n[i] : 0u;
#pragma unroll 4
        for (int m = 0; m < Mc; m++) {
            float iw = fminf(p.z, s_x2[m]) - fmaxf(p.x, s_x1[m]);
            float ih = fminf(p.w, s_y2[m]) - fmaxf(p.y, s_y1[m]);
            bool hit = have && (iw > 0.f) && (ih > 0.f);
            unsigned msk = __ballot_sync(FULLM, hit);
            if (msk) {
                int leader = __ffs(msk) - 1;
                unsigned base = 0;
                if (lane == leader)
                    base = atomicAdd(&g_cnt_m[b * Mc + m], (unsigned)__popc(msk));
                base = __shfl_sync(FULLM, base, leader);
                if (hit)
                    g_list[(size_t)(b * Mc + m) * Nmax + base + __popc(msk & lmask)] = n;
            }
        }
    }
}

// ---------------------------------------------------------------------------
// Kernel 3: per-(b,m) exact top-10 ciou over the survivor list, scatter
// positive values via atomicMax on float bits (order-preserving, commutative).
// ---------------------------------------------------------------------------
__global__ __launch_bounds__(256) void k_ciou(const float* __restrict__ targets, int N) {
    const int m = blockIdx.x;
    const int b = blockIdx.y;
    const int bm = b * Mc + m;
    const int tid  = threadIdx.x;
    const int lane = tid & 31;
    const int wid  = tid >> 5;

    const float* t = targets + (size_t)bm * 4;
    const float x21 = t[0], y21 = t[1], x22 = t[2], y22 = t[3];
    const float w2 = x22 - x21, h2 = y22 - y21;
    const float area2 = w2 * h2;
    const float at2 = atanf(__fdividef(w2, h2 + EPSL));
    const float sx = x21 + x22, sy = y21 + y22;
    const float VP = 4.0f / (float)(M_PI * M_PI);

    unsigned cnt = g_cnt_m[bm];
    if (cnt > (unsigned)N) cnt = (unsigned)N;

    unsigned long long top[10];
#pragma unroll
    for (int j = 0; j < 10; j++) top[j] = 0ull;

    const float4* __restrict__ pb = g_pb + (size_t)b * N;
    const float*  __restrict__ a1 = g_at1 + (size_t)b * N;
    const unsigned* __restrict__ lst = g_list + (size_t)bm * Nmax;

    for (unsigned i = tid; i < cnt; i += 256) {
        unsigned n = lst[i];
        float4 p = pb[n];
        float at1 = a1[n];
        float w1 = p.z - p.x, h1 = p.w - p.y;

        float iw = fminf(p.z, x22) - fmaxf(p.x, x21); iw = fmaxf(iw, 0.f);
        float ih = fminf(p.w, y22) - fmaxf(p.y, y21); ih = fmaxf(ih, 0.f);
        float inter = iw * ih;
        float uni = w1 * h1 + area2 - inter + EPSL;
        float iou = __fdividef(inter, uni);

        float cw = fmaxf(p.z, x22) - fminf(p.x, x21);
        float ch = fmaxf(p.w, y22) - fminf(p.y, y21);
        float c2 = cw * cw + ch * ch + EPSL;

        float dx = sx - p.x - p.z;
        float dy = sy - p.y - p.w;
        float rho2 = (dx * dx + dy * dy) * 0.25f;

        float d = at2 - at1;
        float v = VP * d * d;
        float av = __fdividef(v * v, v - iou + 1.0f + EPSL);
        float ciou = iou - __fdividef(rho2, c2) - av;

        unsigned u = __float_as_uint(ciou);
        unsigned key = (u & 0x80000000u) ? ~u : (u | 0x80000000u);
        unsigned long long pk =
            ((unsigned long long)key << 32) | (unsigned long long)(0xFFFFFFFFu - n);

        if (pk > top[9]) {
#pragma unroll
            for (int j = 0; j < 10; j++) {
                if (pk > top[j]) { unsigned long long tmp = top[j]; top[j] = pk; pk = tmp; }
            }
        }
    }

    __shared__ unsigned long long cand[2560];
    __shared__ unsigned long long wval[8];
    __shared__ int                wpos[8];
    __shared__ unsigned long long s_best;
    __shared__ int                s_bpos;

#pragma unroll
    for (int j = 0; j < 10; j++) cand[tid * 10 + j] = top[j];
    __syncthreads();

    for (int round = 0; round < 10; ++round) {
        unsigned long long mx = 0ull; int mp = tid * 10;
#pragma unroll
        for (int j = 0; j < 10; j++) {
            unsigned long long c = cand[tid * 10 + j];
            if (c > mx) { mx = c; mp = tid * 10 + j; }
        }
#pragma unroll
        for (int off = 16; off > 0; off >>= 1) {
            unsigned long long ov = __shfl_down_sync(FULLM, mx, off);
            int op = __shfl_down_sync(FULLM, mp, off);
            if (ov > mx) { mx = ov; mp = op; }
        }
        if (lane == 0) { wval[wid] = mx; wpos[wid] = mp; }
        __syncthreads();
        if (wid == 0) {
            unsigned long long v2 = (lane < 8) ? wval[lane] : 0ull;
            int p2 = (lane < 8) ? wpos[lane] : 0;
#pragma unroll
            for (int off = 4; off > 0; off >>= 1) {
                unsigned long long ov = __shfl_down_sync(FULLM, v2, off);
                int op = __shfl_down_sync(FULLM, p2, off);
                if (ov > v2) { v2 = ov; p2 = op; }
            }
            if (lane == 0) { s_best = v2; s_bpos = p2; }
        }
        __syncthreads();
        unsigned long long best = s_best;
        int bp = s_bpos;
        unsigned key = (unsigned)(best >> 32);
        if (key <= 0x80000000u) break;   // value <= 0: nothing left to scatter

        if (tid == 0) {
            unsigned n = 0xFFFFFFFFu - (unsigned)(best & 0xFFFFFFFFull);
            atomicMax(&g_it[(size_t)b * N + n], key ^ 0x80000000u);
        }
        if (tid == bp / 10) cand[bp] = 0ull;
        __syncthreads();
    }
}

// ---------------------------------------------------------------------------
// Kernel 4: parallel per-slice reductions, grid (NCH, B). Last block does the
// deterministic fixed-order final combine.
// ---------------------------------------------------------------------------
__global__ __launch_bounds__(256) void k_reduce(const float* __restrict__ scores, int N,
                                                float* out, int out_size) {
    const int c = blockIdx.x;
    const int b = blockIdx.y;
    const int tid = threadIdx.x;
    const int L = (N + NCH - 1) / NCH;
    const int n0 = c * L;
    const int n1 = min(n0 + L, N);

    float np = 0.f, bs = 0.f, bc = 0.f;
    const unsigned int* __restrict__ it = g_it + (size_t)b * N;
    const float* __restrict__ sc = scores + (size_t)b * N;
    for (int n = n0 + tid; n < n1; n += 256) {
        float iv = __uint_as_float(it[n]);
        float s = sc[n];
        if (iv > 0.f) { np += 1.f; bs += 1.f - iv; }
        bc += fmaxf(s, 0.f) - s * iv + __logf(1.f + __expf(-fabsf(s)));
    }
    __shared__ float r0[256], r1[256], r2[256];
    __shared__ int s_last;
    r0[tid] = np; r1[tid] = bs; r2[tid] = bc;
    __syncthreads();
    for (int s = 128; s > 0; s >>= 1) {
        if (tid < s) { r0[tid] += r0[tid + s]; r1[tid] += r1[tid + s]; r2[tid] += r2[tid + s]; }
        __syncthreads();
    }
    if (tid == 0) {
        int slot = b * NCH + c;
        g_part2[slot * 3 + 0] = r0[0];
        g_part2[slot * 3 + 1] = r1[0];
        g_part2[slot * 3 + 2] = r2[0];
        __threadfence();
        unsigned int done = atomicAdd(&g_cnt, 1u);
        s_last = (done == (unsigned)(NCH * Bc - 1)) ? 1 : 0;
    }
    __syncthreads();
    if (!s_last) return;

    // Final combine (deterministic fixed order) in the last block.
    __shared__ float f0[Bc * NCH], f1[Bc * NCH], f2[Bc * NCH];
    __shared__ float bx[Bc], ob[Bc];
    for (int i = tid; i < Bc * NCH; i += 256) {
        f0[i] = g_part2[i * 3 + 0];
        f1[i] = g_part2[i * 3 + 1];
        f2[i] = g_part2[i * 3 + 2];
    }
    __syncthreads();
    if (tid < Bc) {
        float nps = 0.f, bss = 0.f, bcs = 0.f;
        for (int cc = 0; cc < NCH; cc++) {
            nps += f0[tid * NCH + cc];
            bss += f1[tid * NCH + cc];
            bcs += f2[tid * NCH + cc];
        }
        bx[tid] = (nps > 0.f) ? __fdividef(bss, fmaxf(nps, 1.f)) : 0.f;
        ob[tid] = bcs / (float)N;
    }
    __syncthreads();
    if (tid == 0) {
        float box = 0.f, obj = 0.f;
        for (int bb = 0; bb < Bc; bb++) { box += bx[bb]; obj += ob[bb]; }
        float total = (7.5f * box + 1.0f * obj) / (float)Bc;
        out[0] = total;
        if (out_size > 1) out[1] = box;
        if (out_size > 2) out[2] = obj;
    }
}

extern "C" void kernel_launch(void* const* d_in, const int* in_sizes, int n_in,
                              void* d_out, int out_size) {
    const float* boxes   = (const float*)d_in[0];   // [8, 64, N]
    const float* scores  = (const float*)d_in[1];   // [8, N]
    const float* targets = (const float*)d_in[2];   // [8, 64, 4]
    int N = in_sizes[1] / Bc;
    if (N > Nmax) N = Nmax;

    if ((N & 3) == 0) {
        int tot = Bc * (N >> 2);
        k_decode4<<<(tot + 255) / 256, 256>>>(boxes, N);
    } else {
        int tot = Bc * N;
        k_decode1<<<(tot + 255) / 256, 256>>>(boxes, N);
    }
    dim3 gf((N + CHUNK - 1) / CHUNK, Bc);
    k_filter<<<gf, 256>>>(targets, N);
    dim3 gc(Mc, Bc);
    k_ciou<<<gc, 256>>>(targets, N);
    dim3 gr(NCH, Bc);
    k_reduce<<<gr, 256>>>(scores, N, (float*)d_out, out_size);
}